// round 6
// baseline (speedup 1.0000x reference)
#include <cuda_runtime.h>
#include <cuda_bf16.h>
#include <cstdint>

#define NB    32
#define LP    2048
#define LDRG  256
#define DD    512
#define GPNUM 512

typedef unsigned short u16;

// ======================= scratch (floats) =======================
//  S    0         (33554432)  alpha bf16 hi|lo per (b,h) row
//  QPh 33554432  QPl 37748736  KPh 41943040  KPl 46137344
//  VPh 50331648  VPl 54525952
//  QDh 58720256  QDl 60817408  KDh 62914560  KDl 65011712
//  VDh 67108864  VDl 69206016
//  PGH 71303168  PGL 75497472  DRH 79691776  DRL 81788928
//  WH  83886080  WL  84672512
__device__ float g_scratch[85458944];
__device__ unsigned char g_masks[24576];
__device__ int g_flag;

__device__ __forceinline__ u16 bf16bits(float x) {
  __nv_bfloat16 h = __float2bfloat16_rn(x);
  return *reinterpret_cast<u16*>(&h);
}
__device__ __forceinline__ float bf16val(u16 b) {
  __nv_bfloat16 h = *reinterpret_cast<__nv_bfloat16*>(&b);
  return __bfloat162float(h);
}
__device__ __forceinline__ void split2(float v0, float v1, uint32_t& hi, uint32_t& lo) {
  u16 h0 = bf16bits(v0), h1 = bf16bits(v1);
  u16 l0 = bf16bits(v0 - bf16val(h0)), l1 = bf16bits(v1 - bf16val(h1));
  hi = (uint32_t)h0 | ((uint32_t)h1 << 16);
  lo = (uint32_t)l0 | ((uint32_t)l1 << 16);
}

// ======================= masks =======================
__device__ __forceinline__ bool read_mask(const void* p, int i, int f) {
  if (f == 0) return ((const unsigned char*)p)[i] != 0;
  if (f == 1) return ((const int*)p)[i] != 0;
  return ((const float*)p)[i] != 0.0f;
}
__global__ void detect_kernel(const unsigned char* __restrict__ p) {
  int big = 0, off = 0;
  for (int i = 0; i < 1024; ++i) {
    unsigned char c = p[i];
    big |= (c > 1) ? 1 : 0;
    off |= (c != 0 && (i & 3) != 0) ? 1 : 0;
  }
  g_flag = big ? 2 : (off ? 0 : 1);
}
__global__ void mask_kernel(const void* __restrict__ mp, const void* __restrict__ md,
                            float* __restrict__ outMP, float* __restrict__ outMD) {
  int f = g_flag;
  int idx = blockIdx.x * blockDim.x + threadIdx.x;
  if (idx < NB * GPNUM) {
    int b = idx / GPNUM, g = idx % GPNUM;
    int base = b * LP + g * 4;
    bool any = false;
#pragma unroll
    for (int r = 0; r < 4; ++r) any = any || read_mask(mp, base + r, f);
    g_masks[idx] = any ? 1 : 0;
    outMP[idx] = any ? 1.0f : 0.0f;
  } else {
    int j = idx - NB * GPNUM;
    if (j < NB * LDRG) {
      bool v = read_mask(md, j, f);
      g_masks[16384 + j] = v ? 1 : 0;
      outMD[j] = v ? 1.0f : 0.0f;
    }
  }
}

// ============== grouping + bf16 hi/lo split (vectorized) ==============
__global__ void group_bf16_v4(const float* __restrict__ P,
                              uint2* __restrict__ H, uint2* __restrict__ L) {
  int idx = blockIdx.x * 256 + threadIdx.x;   // 2097152 total (4 elems each)
  int d4 = idx & 127;
  int g = (idx >> 7) & 511;
  int b = idx >> 16;
  const float* p = P + ((size_t)b * LP + (size_t)g * 4) * DD + d4 * 4;
  float4 x0 = *(const float4*)p;
  float4 x1 = *(const float4*)(p + 512);
  float4 x2 = *(const float4*)(p + 1024);
  float4 x3 = *(const float4*)(p + 1536);
  float v0 = 0.25f * (x0.x + x1.x + x2.x + x3.x);
  float v1 = 0.25f * (x0.y + x1.y + x2.y + x3.y);
  float v2 = 0.25f * (x0.z + x1.z + x2.z + x3.z);
  float v3 = 0.25f * (x0.w + x1.w + x2.w + x3.w);
  uint32_t h01, l01, h23, l23;
  split2(v0, v1, h01, l01);
  split2(v2, v3, h23, l23);
  H[idx] = make_uint2(h01, h23);
  L[idx] = make_uint2(l01, l23);
}

__global__ void cvt_bf16_v4(const float4* __restrict__ X, int n4,
                            uint2* __restrict__ H, uint2* __restrict__ L) {
  int i = blockIdx.x * 256 + threadIdx.x;
  if (i >= n4) return;
  float4 x = X[i];
  uint32_t h01, l01, h23, l23;
  split2(x.x, x.y, h01, l01);
  split2(x.z, x.w, h23, l23);
  H[i] = make_uint2(h01, h23);
  L[i] = make_uint2(l01, l23);
}

// ======================= HMMA macro =======================
#define MMA_BF16(c, a, b)                                                      \
  asm volatile("mma.sync.aligned.m16n8k16.row.col.f32.bf16.bf16.f32 "          \
               "{%0,%1,%2,%3}, {%4,%5,%6,%7}, {%8,%9}, {%0,%1,%2,%3};"         \
               : "+f"((c)[0]), "+f"((c)[1]), "+f"((c)[2]), "+f"((c)[3])        \
               : "r"((a)[0]), "r"((a)[1]), "r"((a)[2]), "r"((a)[3]),           \
                 "r"((b)[0]), "r"((b)[1]))

// ====== bf16x3 projection: C[M,512] = A[M,512] @ W[512,512]^T, bf16 hi/lo out ======
__global__ __launch_bounds__(256) void gemm_proj_mma(
    const u16* __restrict__ Ah, const u16* __restrict__ Al,
    const u16* __restrict__ Wh, const u16* __restrict__ Wl,
    u16* __restrict__ Ch, u16* __restrict__ Cl) {
  __shared__ __align__(16) u16 Ahs[128][40];
  __shared__ __align__(16) u16 Als[128][40];
  __shared__ __align__(16) u16 Bhs[64][40];
  __shared__ __align__(16) u16 Bls[64][40];

  const int tid = threadIdx.x;
  const int w = tid >> 5, lane = tid & 31;
  const int g = lane >> 2, t4 = lane & 3;
  const int wm = (w >> 1) * 32, wn = (w & 1) * 32;
  const int mBase = blockIdx.x * 128;
  const int nBase = blockIdx.y * 64;

  float acc[2][4][4];
#pragma unroll
  for (int mi = 0; mi < 2; ++mi)
#pragma unroll
    for (int j = 0; j < 4; ++j)
#pragma unroll
      for (int q = 0; q < 4; ++q) acc[mi][j][q] = 0.0f;

  for (int k0 = 0; k0 < 512; k0 += 32) {
#pragma unroll
    for (int u = tid; u < 512; u += 256) {
      int row = u >> 2, seg = u & 3;
      size_t ga = (size_t)(mBase + row) * 512 + k0 + seg * 8;
      *(uint4*)&Ahs[row][seg * 8] = *(const uint4*)(Ah + ga);
      *(uint4*)&Als[row][seg * 8] = *(const uint4*)(Al + ga);
    }
    if (tid < 256) {
      int row = tid >> 2, seg = tid & 3;
      size_t ga = (size_t)(nBase + row) * 512 + k0 + seg * 8;
      *(uint4*)&Bhs[row][seg * 8] = *(const uint4*)(Wh + ga);
      *(uint4*)&Bls[row][seg * 8] = *(const uint4*)(Wl + ga);
    }
    __syncthreads();
#pragma unroll
    for (int kk = 0; kk < 32; kk += 16) {
      const int kb = kk + t4 * 2;
      uint32_t ah[2][4], al[2][4];
#pragma unroll
      for (int mi = 0; mi < 2; ++mi) {
        int r0 = wm + mi * 16 + g, r1 = r0 + 8;
        ah[mi][0] = *(const uint32_t*)&Ahs[r0][kb];
        ah[mi][1] = *(const uint32_t*)&Ahs[r1][kb];
        ah[mi][2] = *(const uint32_t*)&Ahs[r0][kb + 8];
        ah[mi][3] = *(const uint32_t*)&Ahs[r1][kb + 8];
        al[mi][0] = *(const uint32_t*)&Als[r0][kb];
        al[mi][1] = *(const uint32_t*)&Als[r1][kb];
        al[mi][2] = *(const uint32_t*)&Als[r0][kb + 8];
        al[mi][3] = *(const uint32_t*)&Als[r1][kb + 8];
      }
      uint32_t bh[4][2], bl[4][2];
#pragma unroll
      for (int j = 0; j < 4; ++j) {
        int n = wn + j * 8 + g;
        bh[j][0] = *(const uint32_t*)&Bhs[n][kb];
        bh[j][1] = *(const uint32_t*)&Bhs[n][kb + 8];
        bl[j][0] = *(const uint32_t*)&Bls[n][kb];
        bl[j][1] = *(const uint32_t*)&Bls[n][kb + 8];
      }
#pragma unroll
      for (int mi = 0; mi < 2; ++mi)
#pragma unroll
        for (int j = 0; j < 4; ++j) {
          MMA_BF16(acc[mi][j], ah[mi], bh[j]);
          MMA_BF16(acc[mi][j], ah[mi], bl[j]);
          MMA_BF16(acc[mi][j], al[mi], bh[j]);
        }
    }
    __syncthreads();
  }

#pragma unroll
  for (int mi = 0; mi < 2; ++mi) {
    int row = mBase + wm + mi * 16 + g;
#pragma unroll
    for (int j = 0; j < 4; ++j) {
      int col = nBase + wn + j * 8 + t4 * 2;
      uint32_t hi, lo;
      split2(acc[mi][j][0], acc[mi][j][1], hi, lo);
      *(uint32_t*)(Ch + (size_t)row * 512 + col) = hi;
      *(uint32_t*)(Cl + (size_t)row * 512 + col) = lo;
      split2(acc[mi][j][2], acc[mi][j][3], hi, lo);
      *(uint32_t*)(Ch + (size_t)(row + 8) * 512 + col) = hi;
      *(uint32_t*)(Cl + (size_t)(row + 8) * 512 + col) = lo;
    }
  }
}

// ====== FUSED logits + softmax ======
// Block: 32 query rows x full LK per (b,h). Writes bf16 hi|lo alpha into S rows.
template <int LK>
__global__ __launch_bounds__(256) void attn_score_kernel(
    const u16* __restrict__ Qh, const u16* __restrict__ Ql,
    const u16* __restrict__ Kh, const u16* __restrict__ Kl,
    float* __restrict__ S,
    const unsigned char* __restrict__ mq, const unsigned char* __restrict__ mk,
    int Lq) {
  constexpr int NF = LK / 64;  // 8-col frags per warp
  extern __shared__ __align__(16) char dyns[];
  u16* Ahs = (u16*)dyns;                       // [32][40]
  u16* Als = (u16*)(dyns + 2560);
  u16* Bhs = (u16*)(dyns + 5120);              // [LK][40]
  u16* Bls = (u16*)(dyns + 5120 + LK * 80);
  float* red = (float*)(dyns + 5120 + (size_t)LK * 160);  // [32][8]
  float* redf = red + 256;                                 // [32]

  const int tid = threadIdx.x;
  const int w = tid >> 5, lane = tid & 31;
  const int g = lane >> 2, t4 = lane & 3;
  const int wn = w * (LK / 8);
  const int mBase = blockIdx.x * 32;
  const int z = blockIdx.y;
  const int b = z >> 3, h = z & 7;
  const u16* Ahg = Qh + (size_t)b * Lq * 512 + h * 64;
  const u16* Alg = Ql + (size_t)b * Lq * 512 + h * 64;
  const u16* Bhg = Kh + (size_t)b * LK * 512 + h * 64;
  const u16* Blg = Kl + (size_t)b * LK * 512 + h * 64;
  const unsigned char* mqb = mq + b * Lq;
  const unsigned char* mkb = mk + b * LK;

  float acc[2][NF][4];
#pragma unroll
  for (int mi = 0; mi < 2; ++mi)
#pragma unroll
    for (int j = 0; j < NF; ++j)
#pragma unroll
      for (int q = 0; q < 4; ++q) acc[mi][j][q] = 0.0f;

#pragma unroll
  for (int k0 = 0; k0 < 64; k0 += 32) {
    // A: 32 rows x 32 k, hi & lo
    if (tid < 128) {
      int row = tid >> 2, seg = tid & 3;
      *(uint4*)&Ahs[row * 40 + seg * 8] =
          *(const uint4*)(Ahg + (size_t)(mBase + row) * 512 + k0 + seg * 8);
    } else {
      int u = tid - 128;
      int row = u >> 2, seg = u & 3;
      *(uint4*)&Als[row * 40 + seg * 8] =
          *(const uint4*)(Alg + (size_t)(mBase + row) * 512 + k0 + seg * 8);
    }
    // B: LK rows x 32 k, hi & lo
    for (int u = tid; u < LK * 4; u += 256) {
      int row = u >> 2, seg = u & 3;
      *(uint4*)&Bhs[row * 40 + seg * 8] =
          *(const uint4*)(Bhg + (size_t)row * 512 + k0 + seg * 8);
    }
    for (int u = tid; u < LK * 4; u += 256) {
      int row = u >> 2, seg = u & 3;
      *(uint4*)&Bls[row * 40 + seg * 8] =
          *(const uint4*)(Blg + (size_t)row * 512 + k0 + seg * 8);
    }
    __syncthreads();
#pragma unroll
    for (int kk = 0; kk < 32; kk += 16) {
      const int kb = kk + t4 * 2;
      uint32_t ah[2][4], al[2][4];
#pragma unroll
      for (int mi = 0; mi < 2; ++mi) {
        int r0 = mi * 16 + g, r1 = r0 + 8;
        ah[mi][0] = *(const uint32_t*)&Ahs[r0 * 40 + kb];
        ah[mi][1] = *(const uint32_t*)&Ahs[r1 * 40 + kb];
        ah[mi][2] = *(const uint32_t*)&Ahs[r0 * 40 + kb + 8];
        ah[mi][3] = *(const uint32_t*)&Ahs[r1 * 40 + kb + 8];
        al[mi][0] = *(const uint32_t*)&Als[r0 * 40 + kb];
        al[mi][1] = *(const uint32_t*)&Als[r1 * 40 + kb];
        al[mi][2] = *(const uint32_t*)&Als[r0 * 40 + kb + 8];
        al[mi][3] = *(const uint32_t*)&Als[r1 * 40 + kb + 8];
      }
#pragma unroll
      for (int j = 0; j < NF; ++j) {
        int n = wn + j * 8 + g;
        uint32_t bh[2] = {*(const uint32_t*)&Bhs[n * 40 + kb],
                          *(const uint32_t*)&Bhs[n * 40 + kb + 8]};
        uint32_t bl[2] = {*(const uint32_t*)&Bls[n * 40 + kb],
                          *(const uint32_t*)&Bls[n * 40 + kb + 8]};
#pragma unroll
        for (int mi = 0; mi < 2; ++mi) {
          MMA_BF16(acc[mi][j], ah[mi], bh);
          MMA_BF16(acc[mi][j], ah[mi], bl);
          MMA_BF16(acc[mi][j], al[mi], bh);
        }
      }
    }
    __syncthreads();
  }

  // ---- mask ----
#pragma unroll
  for (int mi = 0; mi < 2; ++mi) {
    float p0 = mqb[mBase + mi * 16 + g] ? 0.0f : 1.0e6f;
    float p1 = mqb[mBase + mi * 16 + g + 8] ? 0.0f : 1.0e6f;
#pragma unroll
    for (int j = 0; j < NF; ++j) {
      int c = wn + j * 8 + t4 * 2;
      float c0 = mkb[c] ? 0.0f : 1.0e6f;
      float c1 = mkb[c + 1] ? 0.0f : 1.0e6f;
      acc[mi][j][0] -= fmaxf(p0, c0);
      acc[mi][j][1] -= fmaxf(p0, c1);
      acc[mi][j][2] -= fmaxf(p1, c0);
      acc[mi][j][3] -= fmaxf(p1, c1);
    }
  }

  // ---- row max: t4 shuffle + cross-warp smem ----
  float m0[2], m1[2];
#pragma unroll
  for (int mi = 0; mi < 2; ++mi) {
    m0[mi] = -3.0e38f; m1[mi] = -3.0e38f;
#pragma unroll
    for (int j = 0; j < NF; ++j) {
      m0[mi] = fmaxf(m0[mi], fmaxf(acc[mi][j][0], acc[mi][j][1]));
      m1[mi] = fmaxf(m1[mi], fmaxf(acc[mi][j][2], acc[mi][j][3]));
    }
#pragma unroll
    for (int o = 1; o <= 2; o <<= 1) {
      m0[mi] = fmaxf(m0[mi], __shfl_xor_sync(0xffffffffu, m0[mi], o));
      m1[mi] = fmaxf(m1[mi], __shfl_xor_sync(0xffffffffu, m1[mi], o));
    }
  }
  if (t4 == 0) {
#pragma unroll
    for (int mi = 0; mi < 2; ++mi) {
      red[(mi * 16 + g) * 8 + w] = m0[mi];
      red[(mi * 16 + g + 8) * 8 + w] = m1[mi];
    }
  }
  __syncthreads();
  if (tid < 32) {
    float m = red[tid * 8];
#pragma unroll
    for (int i = 1; i < 8; ++i) m = fmaxf(m, red[tid * 8 + i]);
    redf[tid] = m;
  }
  __syncthreads();
  float rmax[2][2] = {{redf[g], redf[g + 8]}, {redf[16 + g], redf[24 + g]}};
  __syncthreads();

  // ---- exp + row sum ----
  float s0[2], s1[2];
#pragma unroll
  for (int mi = 0; mi < 2; ++mi) {
    s0[mi] = 0.0f; s1[mi] = 0.0f;
#pragma unroll
    for (int j = 0; j < NF; ++j) {
      acc[mi][j][0] = expf(acc[mi][j][0] - rmax[mi][0]);
      acc[mi][j][1] = expf(acc[mi][j][1] - rmax[mi][0]);
      acc[mi][j][2] = expf(acc[mi][j][2] - rmax[mi][1]);
      acc[mi][j][3] = expf(acc[mi][j][3] - rmax[mi][1]);
      s0[mi] += acc[mi][j][0] + acc[mi][j][1];
      s1[mi] += acc[mi][j][2] + acc[mi][j][3];
    }
#pragma unroll
    for (int o = 1; o <= 2; o <<= 1) {
      s0[mi] += __shfl_xor_sync(0xffffffffu, s0[mi], o);
      s1[mi] += __shfl_xor_sync(0xffffffffu, s1[mi], o);
    }
  }
  if (t4 == 0) {
#pragma unroll
    for (int mi = 0; mi < 2; ++mi) {
      red[(mi * 16 + g) * 8 + w] = s0[mi];
      red[(mi * 16 + g + 8) * 8 + w] = s1[mi];
    }
  }
  __syncthreads();
  if (tid < 32) {
    float s = red[tid * 8];
#pragma unroll
    for (int i = 1; i < 8; ++i) s += red[tid * 8 + i];
    redf[tid] = s;
  }
  __syncthreads();

  // ---- normalize + store bf16 hi|lo ----
  u16* Sbase = (u16*)(S + (size_t)z * Lq * LK);
#pragma unroll
  for (int mi = 0; mi < 2; ++mi) {
    int r0 = mBase + mi * 16 + g, r1 = r0 + 8;
    float inv0 = mqb[r0] ? (1.0f / redf[mi * 16 + g]) : 0.0f;
    float inv1 = mqb[r1] ? (1.0f / redf[mi * 16 + g + 8]) : 0.0f;
    u16* row0 = Sbase + (size_t)r0 * 2 * LK;
    u16* row1 = Sbase + (size_t)r1 * 2 * LK;
#pragma unroll
    for (int j = 0; j < NF; ++j) {
      int c = wn + j * 8 + t4 * 2;
      uint32_t hi, lo;
      split2(acc[mi][j][0] * inv0, acc[mi][j][1] * inv0, hi, lo);
      *(uint32_t*)(row0 + c) = hi;
      *(uint32_t*)(row0 + LK + c) = lo;
      split2(acc[mi][j][2] * inv1, acc[mi][j][3] * inv1, hi, lo);
      *(uint32_t*)(row1 + c) = hi;
      *(uint32_t*)(row1 + LK + c) = lo;
    }
  }
}

// ---- alpha fp32 output: [b,l,k,h] coalesced, from bf16 hi|lo in S ----
template <int LK>
__global__ __launch_bounds__(256) void alpha_out_kernel(
    const float* __restrict__ S, float* __restrict__ alphaOut, int Lq) {
  __shared__ float sbuf[8][LK + 1];
  const int l = blockIdx.x, b = blockIdx.y;
  const int tid = threadIdx.x, w = tid >> 5, lane = tid & 31;
  const u16* arow = (const u16*)(S + ((size_t)(b * 8 + w) * Lq + l) * LK);
#pragma unroll
  for (int i = 0; i < LK / 32; ++i) {
    int k = lane + 32 * i;
    sbuf[w][k] = bf16val(arow[k]) + bf16val(arow[LK + k]);
  }
  __syncthreads();
  const size_t abase = ((size_t)b * Lq + l) * (size_t)(LK * 8);
#pragma unroll 4
  for (int idx = tid; idx < LK * 8; idx += 256) {
    int k = idx >> 3, h = idx & 7;
    alphaOut[abase + idx] = sbuf[h][k];
  }
}

// ====== bf16x3 AV: Out[b,l,h*64+n] = sum_k alpha[b,h,l,k] V[b,k,h*64+n] ======
__global__ __launch_bounds__(256) void gemm_av_mma(
    const float* __restrict__ S, const u16* __restrict__ Vh, const u16* __restrict__ Vl,
    float* __restrict__ Out, int Lq, int Lk) {
  __shared__ __align__(16) u16 Ahs[128][40];
  __shared__ __align__(16) u16 Als[128][40];
  __shared__ __align__(16) u16 Bhs[64][42];
  __shared__ __align__(16) u16 Bls[64][42];

  const int tid = threadIdx.x;
  const int w = tid >> 5, lane = tid & 31;
  const int g = lane >> 2, t4 = lane & 3;
  const int wm = (w >> 1) * 32, wn = (w & 1) * 32;
  const int mBase = blockIdx.x * 128;
  const int z = blockIdx.z;
  const int b = z >> 3, h = z & 7;
  const u16* Abase = (const u16*)(S + (size_t)z * Lq * Lk);
  const size_t vbase = (size_t)b * Lk * 512 + h * 64;
  float* C = Out + (size_t)b * Lq * 512 + h * 64;

  float acc[2][4][4];
#pragma unroll
  for (int mi = 0; mi < 2; ++mi)
#pragma unroll
    for (int j = 0; j < 4; ++j)
#pragma unroll
      for (int q = 0; q < 4; ++q) acc[mi][j][q] = 0.0f;

  for (int k0 = 0; k0 < Lk; k0 += 32) {
#pragma unroll
    for (int u = tid; u < 512; u += 256) {
      int row = u >> 2, seg = u & 3;
      const u16* ar = Abase + (size_t)(mBase + row) * 2 * Lk + k0 + seg * 8;
      *(uint4*)&Ahs[row][seg * 8] = *(const uint4*)ar;
      *(uint4*)&Als[row][seg * 8] = *(const uint4*)(ar + Lk);
    }
#pragma unroll
    for (int u = tid; u < 1024; u += 256) {
      int k = u >> 5, np = (u & 31) * 2;
      size_t ga = vbase + (size_t)(k0 + k) * 512 + np;
      uint32_t vh = *(const uint32_t*)(Vh + ga);
      uint32_t vl = *(const uint32_t*)(Vl + ga);
      Bhs[np][k] = (u16)(vh & 0xffffu);
      Bhs[np + 1][k] = (u16)(vh >> 16);
      Bls[np][k] = (u16)(vl & 0xffffu);
      Bls[np + 1][k] = (u16)(vl >> 16);
    }
    __syncthreads();
#pragma unroll
    for (int kk = 0; kk < 32; kk += 16) {
      const int kb = kk + t4 * 2;
      uint32_t ah[2][4], al[2][4];
#pragma unroll
      for (int mi = 0; mi < 2; ++mi) {
        int r0 = wm + mi * 16 + g, r1 = r0 + 8;
        ah[mi][0] = *(const uint32_t*)&Ahs[r0][kb];
        ah[mi][1] = *(const uint32_t*)&Ahs[r1][kb];
        ah[mi][2] = *(const uint32_t*)&Ahs[r0][kb + 8];
        ah[mi][3] = *(const uint32_t*)&Ahs[r1][kb + 8];
        al[mi][0] = *(const uint32_t*)&Als[r0][kb];
        al[mi][1] = *(const uint32_t*)&Als[r1][kb];
        al[mi][2] = *(const uint32_t*)&Als[r0][kb + 8];
        al[mi][3] = *(const uint32_t*)&Als[r1][kb + 8];
      }
      uint32_t bh[4][2], bl[4][2];
#pragma unroll
      for (int j = 0; j < 4; ++j) {
        int n = wn + j * 8 + g;
        bh[j][0] = *(const uint32_t*)&Bhs[n][kb];
        bh[j][1] = *(const uint32_t*)&Bhs[n][kb + 8];
        bl[j][0] = *(const uint32_t*)&Bls[n][kb];
        bl[j][1] = *(const uint32_t*)&Bls[n][kb + 8];
      }
#pragma unroll
      for (int mi = 0; mi < 2; ++mi)
#pragma unroll
        for (int j = 0; j < 4; ++j) {
          MMA_BF16(acc[mi][j], ah[mi], bh[j]);
          MMA_BF16(acc[mi][j], ah[mi], bl[j]);
          MMA_BF16(acc[mi][j], al[mi], bh[j]);
        }
    }
    __syncthreads();
  }

#pragma unroll
  for (int mi = 0; mi < 2; ++mi) {
    int row = mBase + wm + mi * 16 + g;
#pragma unroll
    for (int j = 0; j < 4; ++j) {
      int col = wn + j * 8 + t4 * 2;
      *(float2*)(C + (size_t)row * 512 + col) = make_float2(acc[mi][j][0], acc[mi][j][1]);
      *(float2*)(C + (size_t)(row + 8) * 512 + col) = make_float2(acc[mi][j][2], acc[mi][j][3]);
    }
  }
}

// ---------------- launch ----------------
extern "C" void kernel_launch(void* const* d_in, const int* in_sizes, int n_in,
                              void* d_out, int out_size) {
  const float* protein = (const float*)d_in[0];
  const float* drug    = (const float*)d_in[1];
  const void*  mpraw   = d_in[2];
  const void*  mdraw   = d_in[3];
  const float* W[6] = {(const float*)d_in[4], (const float*)d_in[5], (const float*)d_in[6],
                       (const float*)d_in[7], (const float*)d_in[8], (const float*)d_in[9]};
  float* out = (float*)d_out;

  float* sc = nullptr;
  cudaGetSymbolAddress((void**)&sc, g_scratch);
  unsigned char* mg = nullptr;
  cudaGetSymbolAddress((void**)&mg, g_masks);

  float* Sb = sc;
  u16* QPh = (u16*)(sc + 33554432); u16* QPl = (u16*)(sc + 37748736);
  u16* KPh = (u16*)(sc + 41943040); u16* KPl = (u16*)(sc + 46137344);
  u16* VPh = (u16*)(sc + 50331648); u16* VPl = (u16*)(sc + 54525952);
  u16* QDh = (u16*)(sc + 58720256); u16* QDl = (u16*)(sc + 60817408);
  u16* KDh = (u16*)(sc + 62914560); u16* KDl = (u16*)(sc + 65011712);
  u16* VDh = (u16*)(sc + 67108864); u16* VDl = (u16*)(sc + 69206016);
  u16* PGH = (u16*)(sc + 71303168); u16* PGL = (u16*)(sc + 75497472);
  u16* DRH = (u16*)(sc + 79691776); u16* DRL = (u16*)(sc + 81788928);
  u16* WHb = (u16*)(sc + 83886080); u16* WLb = (u16*)(sc + 84672512);
  unsigned char* mpg = mg;
  unsigned char* mdg = mg + 16384;

  const size_t OFF_PROT = 0;
  const size_t OFF_DRUG = 8388608;
  const size_t OFF_MP   = 12582912;
  const size_t OFF_MD   = 12599296;
  const size_t OFF_APD  = 12607488;
  const size_t OFF_ADP  = 46161920;

  static int attr_done = 0;
  const int SM256 = 5120 + 256 * 160 + 1152;  // 47232
  const int SM512 = 5120 + 512 * 160 + 1152;  // 88192
  if (!attr_done) {
    cudaFuncSetAttribute(attn_score_kernel<256>,
                         cudaFuncAttributeMaxDynamicSharedMemorySize, SM256);
    cudaFuncSetAttribute(attn_score_kernel<512>,
                         cudaFuncAttributeMaxDynamicSharedMemorySize, SM512);
    attr_done = 1;
  }

  detect_kernel<<<1, 1>>>((const unsigned char*)mpraw);
  mask_kernel<<<96, 256>>>(mpraw, mdraw, out + OFF_MP, out + OFF_MD);
  group_bf16_v4<<<8192, 256>>>(protein, (uint2*)PGH, (uint2*)PGL);
  cvt_bf16_v4<<<4096, 256>>>((const float4*)drug, 1048576, (uint2*)DRH, (uint2*)DRL);
  for (int i = 0; i < 6; ++i)
    cvt_bf16_v4<<<256, 256>>>((const float4*)W[i], 65536,
                              (uint2*)(WHb + (size_t)i * 262144),
                              (uint2*)(WLb + (size_t)i * 262144));

  // projections -> bf16 hi/lo
  u16* PH[3] = {QPh, KPh, VPh}; u16* PL[3] = {QPl, KPl, VPl};
  for (int i = 0; i < 3; ++i)
    gemm_proj_mma<<<dim3(128, 8), 256>>>(PGH, PGL, WHb + (size_t)i * 262144,
                                         WLb + (size_t)i * 262144, PH[i], PL[i]);
  u16* DH[3] = {QDh, KDh, VDh}; u16* DL[3] = {QDl, KDl, VDl};
  for (int i = 0; i < 3; ++i)
    gemm_proj_mma<<<dim3(64, 8), 256>>>(DRH, DRL, WHb + (size_t)(i + 3) * 262144,
                                        WLb + (size_t)(i + 3) * 262144, DH[i], DL[i]);

  // protein->drug: Lq=512, Lk=256
  attn_score_kernel<256><<<dim3(16, 256), 256, SM256>>>(QPh, QPl, KDh, KDl, Sb, mpg, mdg, 512);
  alpha_out_kernel<256><<<dim3(512, 32), 256>>>(Sb, out + OFF_APD, 512);
  gemm_av_mma<<<dim3(4, 1, 256), 256>>>(Sb, VDh, VDl, out + OFF_PROT, 512, 256);

  // drug->protein: Lq=256, Lk=512
  attn_score_kernel<512><<<dim3(8, 256), 256, SM512>>>(QDh, QDl, KPh, KPl, Sb, mdg, mpg, 256);
  alpha_out_kernel<512><<<dim3(256, 32), 256>>>(Sb, out + OFF_ADP, 256);
  gemm_av_mma<<<dim3(2, 1, 256), 256>>>(Sb, VPh, VPl, out + OFF_DRUG, 256, 512);

  (void)in_sizes; (void)n_in; (void)out_size;
}